// round 1
// baseline (speedup 1.0000x reference)
#include <cuda_runtime.h>
#include <cuda_bf16.h>
#include <stdint.h>

// Problem constants (fixed by setup_inputs)
#define BB   32
#define SS   8192
#define CC   256
#define KK   64
#define NCOL (BB * CC)       // 8192 columns
#define CAP  512             // candidate buffer capacity per column

// Static threshold: value >= 2.0f  <=>  monotone key >= 0xC0000000
#define K0 0xC0000000u

// Scratch (device globals — allocation-free per harness rules)
__device__ unsigned int       g_count[NCOL];
__device__ unsigned long long g_cand[(size_t)NCOL * CAP];   // ~33.5 MB

__device__ __forceinline__ unsigned int fkey(float f) {
    unsigned int u = __float_as_uint(f);
    return (u & 0x80000000u) ? ~u : (u | 0x80000000u);
}
__device__ __forceinline__ float fval(unsigned int key) {
    unsigned int u = (key & 0x80000000u) ? (key & 0x7FFFFFFFu) : ~key;
    return __uint_as_float(u);
}

// ---------------------------------------------------------------------------
// Pass A: single full coalesced read; collect candidates >= 2.0 per column.
// ---------------------------------------------------------------------------
__global__ void collect_kernel(const float* __restrict__ x) {
    const int nq = BB * SS * CC / 4;          // float4 count
    const float4* __restrict__ x4 = reinterpret_cast<const float4*>(x);
    for (int q = blockIdx.x * blockDim.x + threadIdx.x; q < nq;
         q += gridDim.x * blockDim.x) {
        float4 v = x4[q];
        int c4  = q & 63;                     // CC/4 = 64
        int row = q >> 6;
        int s   = row & (SS - 1);
        int b   = row >> 13;                  // SS = 8192
        int colbase = b * CC + c4 * 4;
        float vals[4] = {v.x, v.y, v.z, v.w};
#pragma unroll
        for (int l = 0; l < 4; l++) {
            unsigned int key = fkey(vals[l]);
            if (key >= K0) {
                int col = colbase + l;
                unsigned int pos = atomicAdd(&g_count[col], 1u);
                if (pos < CAP) {
                    g_cand[(size_t)col * CAP + pos] =
                        ((unsigned long long)key << 32) | (unsigned int)s;
                }
            }
        }
    }
}

// ---------------------------------------------------------------------------
// Kernel B: one block per column. Fast path: select top-K among candidates,
// write in original s-order. Fallback: exact bitwise select over raw column.
// ---------------------------------------------------------------------------
__global__ void finalize_kernel(const float* __restrict__ x,
                                float* __restrict__ out) {
    const int col = blockIdx.x;
    const int b = col >> 8;                   // CC = 256
    const int c = col & (CC - 1);
    const int tid = threadIdx.x;

    __shared__ unsigned long long sc[CAP];
    __shared__ unsigned long long sV;
    __shared__ int scnt[256];

    unsigned int n = g_count[col];

    if (n >= KK && n <= CAP) {
        // ---------- fast path ----------
        for (unsigned int i = tid; i < n; i += 256)
            sc[i] = g_cand[(size_t)col * CAP + i];
        __syncthreads();

        // k-th largest composite (rank K-1 by #greater); composites distinct.
        for (unsigned int i = tid; i < n; i += 256) {
            unsigned long long ci = sc[i];
            int r = 0;
            for (unsigned int j = 0; j < n; j++) r += (sc[j] > ci);
            if (r == KK - 1) sV = ci;
        }
        __syncthreads();
        unsigned long long V = sV;

        // For each selected element, output position = #selected with smaller s.
        for (unsigned int i = tid; i < n; i += 256) {
            unsigned long long ci = sc[i];
            if (ci >= V) {
                unsigned int si = (unsigned int)ci;     // low 32 bits = s
                int pos = 0;
                for (unsigned int j = 0; j < n; j++) {
                    unsigned long long cj = sc[j];
                    pos += (int)((cj >= V) & ((unsigned int)cj < si));
                }
                out[((size_t)b * KK + pos) * CC + c] = fval((unsigned int)(ci >> 32));
            }
        }
    } else {
        // ---------- exact fallback (expected never on this data) ----------
        // Build V = K-th largest composite bit-by-bit (64 count passes).
        unsigned long long V = 0;
        for (int bit = 63; bit >= 0; bit--) {
            unsigned long long cand = V | (1ull << bit);
            int local = 0;
            for (int i = tid; i < SS; i += 256) {
                float f = x[((size_t)b * SS + i) * CC + c];
                unsigned long long comp =
                    ((unsigned long long)fkey(f) << 32) | (unsigned int)i;
                local += (comp >= cand);
            }
            scnt[tid] = local;
            __syncthreads();
            for (int st = 128; st > 0; st >>= 1) {
                if (tid < st) scnt[tid] += scnt[tid + st];
                __syncthreads();
            }
            int cnt = scnt[0];
            __syncthreads();
            if (cnt >= KK) V = cand;
        }
        // Ordered write: thread t owns contiguous s-range, exclusive scan.
        const int per = SS / 256;             // 32
        int lcnt = 0;
        for (int i = 0; i < per; i++) {
            int s = tid * per + i;
            float f = x[((size_t)b * SS + s) * CC + c];
            unsigned long long comp =
                ((unsigned long long)fkey(f) << 32) | (unsigned int)s;
            lcnt += (comp >= V);
        }
        scnt[tid] = lcnt;
        __syncthreads();
        // Hillis–Steele inclusive scan -> exclusive base
        for (int off = 1; off < 256; off <<= 1) {
            int v = scnt[tid];
            int w = (tid >= off) ? scnt[tid - off] : 0;
            __syncthreads();
            scnt[tid] = v + w;
            __syncthreads();
        }
        int base = scnt[tid] - lcnt;
        for (int i = 0; i < per; i++) {
            int s = tid * per + i;
            float f = x[((size_t)b * SS + s) * CC + c];
            unsigned long long comp =
                ((unsigned long long)fkey(f) << 32) | (unsigned int)s;
            if (comp >= V) {
                if (base < KK)
                    out[((size_t)b * KK + base) * CC + c] = f;
                base++;
            }
        }
    }
}

extern "C" void kernel_launch(void* const* d_in, const int* in_sizes, int n_in,
                              void* d_out, int out_size) {
    const float* x = (const float*)d_in[0];
    float* out = (float*)d_out;

    void* cnt_ptr = nullptr;
    cudaGetSymbolAddress(&cnt_ptr, g_count);
    cudaMemsetAsync(cnt_ptr, 0, NCOL * sizeof(unsigned int));

    collect_kernel<<<4096, 256>>>(x);
    finalize_kernel<<<NCOL, 256>>>(x, out);
}

// round 2
// speedup vs baseline: 1.0105x; 1.0105x over previous
#include <cuda_runtime.h>
#include <cuda_bf16.h>
#include <stdint.h>

// Problem constants (fixed by setup_inputs)
#define BB   32
#define SS   8192
#define CC   256
#define KK   64
#define NCOL (BB * CC)       // 8192 columns
#define CAP  512             // candidate buffer capacity per column

// Static threshold: value >= 2.0f  <=>  monotone key >= 0xC0000000
#define K0 0xC0000000u

// Scratch (device globals — allocation-free per harness rules)
__device__ unsigned int       g_count[NCOL];
__device__ unsigned long long g_cand[(size_t)NCOL * CAP];   // ~33.5 MB

__device__ __forceinline__ unsigned int fkey(float f) {
    unsigned int u = __float_as_uint(f);
    return (u & 0x80000000u) ? ~u : (u | 0x80000000u);
}
__device__ __forceinline__ float fval(unsigned int key) {
    unsigned int u = (key & 0x80000000u) ? (key & 0x7FFFFFFFu) : ~key;
    return __uint_as_float(u);
}

// ---------------------------------------------------------------------------
// Pass A: single full coalesced read; collect candidates >= 2.0 per column.
// ---------------------------------------------------------------------------
__global__ void collect_kernel(const float* __restrict__ x) {
    const int nq = BB * SS * CC / 4;          // float4 count
    const float4* __restrict__ x4 = reinterpret_cast<const float4*>(x);
    for (int q = blockIdx.x * blockDim.x + threadIdx.x; q < nq;
         q += gridDim.x * blockDim.x) {
        float4 v = x4[q];
        int c4  = q & 63;                     // CC/4 = 64
        int row = q >> 6;
        int s   = row & (SS - 1);
        int b   = row >> 13;                  // SS = 8192
        int colbase = b * CC + c4 * 4;
        float vals[4] = {v.x, v.y, v.z, v.w};
#pragma unroll
        for (int l = 0; l < 4; l++) {
            unsigned int key = fkey(vals[l]);
            if (key >= K0) {
                int col = colbase + l;
                unsigned int pos = atomicAdd(&g_count[col], 1u);
                if (pos < CAP) {
                    g_cand[(size_t)col * CAP + pos] =
                        ((unsigned long long)key << 32) | (unsigned int)s;
                }
            }
        }
    }
}

// ---------------------------------------------------------------------------
// Kernel B: one block per column. Fast path: select top-K among candidates,
// write in original s-order. Fallback: exact bitwise select over raw column.
// ---------------------------------------------------------------------------
__global__ void finalize_kernel(const float* __restrict__ x,
                                float* __restrict__ out) {
    const int col = blockIdx.x;
    const int b = col >> 8;                   // CC = 256
    const int c = col & (CC - 1);
    const int tid = threadIdx.x;

    __shared__ unsigned long long sc[CAP];
    __shared__ unsigned long long sV;
    __shared__ int scnt[256];

    unsigned int n = g_count[col];

    if (n >= KK && n <= CAP) {
        // ---------- fast path ----------
        for (unsigned int i = tid; i < n; i += 256)
            sc[i] = g_cand[(size_t)col * CAP + i];
        __syncthreads();

        // k-th largest composite (rank K-1 by #greater); composites distinct.
        for (unsigned int i = tid; i < n; i += 256) {
            unsigned long long ci = sc[i];
            int r = 0;
            for (unsigned int j = 0; j < n; j++) r += (sc[j] > ci);
            if (r == KK - 1) sV = ci;
        }
        __syncthreads();
        unsigned long long V = sV;

        // For each selected element, output position = #selected with smaller s.
        for (unsigned int i = tid; i < n; i += 256) {
            unsigned long long ci = sc[i];
            if (ci >= V) {
                unsigned int si = (unsigned int)ci;     // low 32 bits = s
                int pos = 0;
                for (unsigned int j = 0; j < n; j++) {
                    unsigned long long cj = sc[j];
                    pos += (int)((cj >= V) & ((unsigned int)cj < si));
                }
                out[((size_t)b * KK + pos) * CC + c] = fval((unsigned int)(ci >> 32));
            }
        }
    } else {
        // ---------- exact fallback (expected never on this data) ----------
        // Build V = K-th largest composite bit-by-bit (64 count passes).
        unsigned long long V = 0;
        for (int bit = 63; bit >= 0; bit--) {
            unsigned long long cand = V | (1ull << bit);
            int local = 0;
            for (int i = tid; i < SS; i += 256) {
                float f = x[((size_t)b * SS + i) * CC + c];
                unsigned long long comp =
                    ((unsigned long long)fkey(f) << 32) | (unsigned int)i;
                local += (comp >= cand);
            }
            scnt[tid] = local;
            __syncthreads();
            for (int st = 128; st > 0; st >>= 1) {
                if (tid < st) scnt[tid] += scnt[tid + st];
                __syncthreads();
            }
            int cnt = scnt[0];
            __syncthreads();
            if (cnt >= KK) V = cand;
        }
        // Ordered write: thread t owns contiguous s-range, exclusive scan.
        const int per = SS / 256;             // 32
        int lcnt = 0;
        for (int i = 0; i < per; i++) {
            int s = tid * per + i;
            float f = x[((size_t)b * SS + s) * CC + c];
            unsigned long long comp =
                ((unsigned long long)fkey(f) << 32) | (unsigned int)s;
            lcnt += (comp >= V);
        }
        scnt[tid] = lcnt;
        __syncthreads();
        // Hillis–Steele inclusive scan -> exclusive base
        for (int off = 1; off < 256; off <<= 1) {
            int v = scnt[tid];
            int w = (tid >= off) ? scnt[tid - off] : 0;
            __syncthreads();
            scnt[tid] = v + w;
            __syncthreads();
        }
        int base = scnt[tid] - lcnt;
        for (int i = 0; i < per; i++) {
            int s = tid * per + i;
            float f = x[((size_t)b * SS + s) * CC + c];
            unsigned long long comp =
                ((unsigned long long)fkey(f) << 32) | (unsigned int)s;
            if (comp >= V) {
                if (base < KK)
                    out[((size_t)b * KK + base) * CC + c] = f;
                base++;
            }
        }
    }
}

extern "C" void kernel_launch(void* const* d_in, const int* in_sizes, int n_in,
                              void* d_out, int out_size) {
    const float* x = (const float*)d_in[0];
    float* out = (float*)d_out;

    void* cnt_ptr = nullptr;
    cudaGetSymbolAddress(&cnt_ptr, g_count);
    cudaMemsetAsync(cnt_ptr, 0, NCOL * sizeof(unsigned int));

    collect_kernel<<<4096, 256>>>(x);
    finalize_kernel<<<NCOL, 256>>>(x, out);
}

// round 3
// speedup vs baseline: 1.1340x; 1.1223x over previous
#include <cuda_runtime.h>
#include <cuda_bf16.h>
#include <stdint.h>

// Problem constants (fixed by setup_inputs)
#define BB   32
#define SS   8192
#define CC   256
#define KK   64
#define NCOL (BB * CC)       // 8192 columns
#define CAP  256             // candidate buffer capacity per column (1/thread)

#define NTHREADS_TOTAL (4096 * 256)   // collect grid
#define ITERS 16                       // 16.78M float4 / 1M threads

// Threshold 2.1875: P(X>t)=0.0143 -> ~117 candidates/column (sd ~10.7).
// Columns failing (n<KK or n>CAP) fall back to the exact path.
#define THRESH 2.1875f

// Scratch (device globals — allocation-free per harness rules)
__device__ unsigned int       g_count[NCOL];
__device__ unsigned long long g_cand[(size_t)NCOL * CAP];   // 16.8 MB

__device__ __forceinline__ unsigned int fkey(float f) {
    unsigned int u = __float_as_uint(f);
    return (u & 0x80000000u) ? ~u : (u | 0x80000000u);
}

// ---------------------------------------------------------------------------
// Pass A: one full coalesced read. All 16 float4 loads issued up front
// (MLP=16) so the atomic/store tail doesn't serialize the memory stream.
// ---------------------------------------------------------------------------
__global__ void __launch_bounds__(256) collect_kernel(const float* __restrict__ x) {
    const float4* __restrict__ x4 = reinterpret_cast<const float4*>(x);
    const int t = blockIdx.x * blockDim.x + threadIdx.x;

    float4 v[ITERS];
#pragma unroll
    for (int i = 0; i < ITERS; i++)
        v[i] = x4[t + i * NTHREADS_TOTAL];

#pragma unroll
    for (int i = 0; i < ITERS; i++) {
        const int q   = t + i * NTHREADS_TOTAL;
        const int c4  = q & 63;                 // CC/4 = 64 float4 per row
        const int row = q >> 6;                 // (b,s) row index
        const int s   = row & (SS - 1);
        const int b   = row >> 13;              // SS = 8192
        const int colbase = b * CC + (c4 << 2);
        float vals[4] = {v[i].x, v[i].y, v[i].z, v[i].w};
#pragma unroll
        for (int l = 0; l < 4; l++) {
            if (vals[l] >= THRESH) {
                // candidates are positive floats: monotone key = u | signbit
                unsigned int key = __float_as_uint(vals[l]) | 0x80000000u;
                int col = colbase + l;
                unsigned int pos = atomicAdd(&g_count[col], 1u);
                if (pos < CAP)
                    g_cand[(size_t)col * CAP + pos] =
                        ((unsigned long long)key << 32) | (unsigned int)s;
            }
        }
    }
}

// ---------------------------------------------------------------------------
// Kernel B: one block per column.
// Fast path: bitonic-sort 256 composites (invalid -> 0 sink to bottom),
// take top 64, bitonic-sort those by original index s, write out.
// Fallback: exact 64-pass bitwise select over the raw column.
// ---------------------------------------------------------------------------
__global__ void __launch_bounds__(256) finalize_kernel(const float* __restrict__ x,
                                                       float* __restrict__ out) {
    const int col = blockIdx.x;
    const int b = col >> 8;                   // CC = 256
    const int c = col & (CC - 1);
    const int tid = threadIdx.x;

    __shared__ unsigned long long sc[256];
    __shared__ unsigned long long sel[KK];
    __shared__ int scnt[256];

    const unsigned int n = g_count[col];

    if (n >= KK && n <= CAP) {
        // ---------- fast path ----------
        sc[tid] = (tid < n) ? g_cand[(size_t)col * CAP + tid] : 0ull;
        __syncthreads();

        // Bitonic ascending sort of 256 64-bit composites.
        // Valid composites have the top bit set (key >= 0xC00C0000) so the
        // zero padding sinks to the bottom; slots [192..255] = 64 largest.
#pragma unroll
        for (int k2 = 2; k2 <= 256; k2 <<= 1) {
#pragma unroll
            for (int j = k2 >> 1; j > 0; j >>= 1) {
                int ixj = tid ^ j;
                if (ixj > tid) {
                    unsigned long long a = sc[tid], bb2 = sc[ixj];
                    bool up = ((tid & k2) == 0);
                    if ((a > bb2) == up) { sc[tid] = bb2; sc[ixj] = a; }
                }
                __syncthreads();
            }
        }

        if (tid < KK) sel[tid] = sc[256 - KK + tid];
        __syncthreads();

        // Re-sort the 64 selected by low-32 bits (original index s, distinct).
#pragma unroll
        for (int k2 = 2; k2 <= KK; k2 <<= 1) {
#pragma unroll
            for (int j = k2 >> 1; j > 0; j >>= 1) {
                if (tid < KK) {
                    int ixj = tid ^ j;
                    if (ixj > tid) {
                        unsigned long long a = sel[tid], bb2 = sel[ixj];
                        bool up = ((tid & k2) == 0);
                        if (((unsigned int)a > (unsigned int)bb2) == up) {
                            sel[tid] = bb2; sel[ixj] = a;
                        }
                    }
                }
                __syncthreads();
            }
        }

        if (tid < KK) {
            unsigned int key = (unsigned int)(sel[tid] >> 32);
            // candidates are positive: original bits = key & 0x7FFFFFFF
            out[((size_t)b * KK + tid) * CC + c] = __uint_as_float(key & 0x7FFFFFFFu);
        }
    } else {
        // ---------- exact fallback (expected ~never on this data) ----------
        // Build V = K-th largest 64-bit composite bit-by-bit.
        unsigned long long V = 0;
        for (int bit = 63; bit >= 0; bit--) {
            unsigned long long cand = V | (1ull << bit);
            int local = 0;
            for (int i = tid; i < SS; i += 256) {
                float f = x[((size_t)b * SS + i) * CC + c];
                unsigned long long comp =
                    ((unsigned long long)fkey(f) << 32) | (unsigned int)i;
                local += (comp >= cand);
            }
            scnt[tid] = local;
            __syncthreads();
            for (int st = 128; st > 0; st >>= 1) {
                if (tid < st) scnt[tid] += scnt[tid + st];
                __syncthreads();
            }
            int cnt = scnt[0];
            __syncthreads();
            if (cnt >= KK) V = cand;
        }
        // Ordered write: thread t owns contiguous s-range, exclusive scan.
        const int per = SS / 256;             // 32
        int lcnt = 0;
        for (int i = 0; i < per; i++) {
            int s = tid * per + i;
            float f = x[((size_t)b * SS + s) * CC + c];
            unsigned long long comp =
                ((unsigned long long)fkey(f) << 32) | (unsigned int)s;
            lcnt += (comp >= V);
        }
        scnt[tid] = lcnt;
        __syncthreads();
        for (int off = 1; off < 256; off <<= 1) {
            int vv = scnt[tid];
            int w = (tid >= off) ? scnt[tid - off] : 0;
            __syncthreads();
            scnt[tid] = vv + w;
            __syncthreads();
        }
        int base = scnt[tid] - lcnt;
        for (int i = 0; i < per; i++) {
            int s = tid * per + i;
            float f = x[((size_t)b * SS + s) * CC + c];
            unsigned long long comp =
                ((unsigned long long)fkey(f) << 32) | (unsigned int)s;
            if (comp >= V) {
                if (base < KK)
                    out[((size_t)b * KK + base) * CC + c] = f;
                base++;
            }
        }
    }
}

extern "C" void kernel_launch(void* const* d_in, const int* in_sizes, int n_in,
                              void* d_out, int out_size) {
    const float* x = (const float*)d_in[0];
    float* out = (float*)d_out;

    void* cnt_ptr = nullptr;
    cudaGetSymbolAddress(&cnt_ptr, g_count);
    cudaMemsetAsync(cnt_ptr, 0, NCOL * sizeof(unsigned int));

    collect_kernel<<<4096, 256>>>(x);
    finalize_kernel<<<NCOL, 256>>>(x, out);
}